// round 2
// baseline (speedup 1.0000x reference)
#include <cuda_runtime.h>
#include <cstdint>

// ---------------------------------------------------------------------------
// Problem constants
// ---------------------------------------------------------------------------
#define NUM_CLASSES 80
#define B_IMG 8
#define NTOT 20460            // total anchors per image across 5 levels
#define TOPK 1000
#define MAX_PER_IMG 100
#define IMG_H 768.0f
#define IMG_W 1280.0f
#define CLS_OFFSET 4096.0f
#define MAX_RATIO_ANCHOR 13.815510557964274f   // |log(1e-6)|
#define MAX_RATIO_BBOX   4.135166556742356f    // |log(16/1000)|

__device__ __constant__ int   c_HW[5]     = {15360, 3840, 960, 240, 60};
__device__ __constant__ int   c_W[5]      = {160, 80, 40, 20, 10};
__device__ __constant__ int   c_off[5]    = {0, 15360, 19200, 20160, 20400};
__device__ __constant__ float c_stride[5] = {8.f, 16.f, 32.f, 64.f, 128.f};

// ---------------------------------------------------------------------------
// Scratch (device globals; no runtime allocation allowed)
// ---------------------------------------------------------------------------
__device__ float  g_key[B_IMG * NTOT];          // per-anchor masked max score
__device__ int    g_sel[B_IMG * 1024];          // selected anchor ids (sorted)
__device__ float  g_sc[B_IMG * NUM_CLASSES * 1024]; // class-major scores, thresholded
__device__ float4 g_boxes[B_IMG * 1024];        // decoded proposals

// per-class NMS pick lists
__device__ float          g_pick_s[B_IMG * NUM_CLASSES * MAX_PER_IMG];
__device__ unsigned short g_pick_r[B_IMG * NUM_CLASSES * MAX_PER_IMG];
__device__ int            g_pick_cnt[B_IMG * NUM_CLASSES];
__device__ int            g_pick_stk[B_IMG * NUM_CLASSES];

struct Ptrs { const float* p[20]; };

// ---------------------------------------------------------------------------
// Numerics matching jax
// ---------------------------------------------------------------------------
__device__ __forceinline__ float sigf(float x) {
    if (x >= 0.f) return 1.f / (1.f + expf(-x));
    float e = expf(x);
    return e / (1.f + e);
}
__device__ __forceinline__ float dsigf(float x) {
    float s = sigf(x);              // s in (0,1) -> non-negative branch
    return 1.f / (1.f + expf(-s));
}
__device__ __forceinline__ float clampf(float v, float lo, float hi) {
    return fminf(fmaxf(v, lo), hi);
}

// ---------------------------------------------------------------------------
// Kernel 1: per-anchor masked max-class score (key for top-k)
// ---------------------------------------------------------------------------
__global__ __launch_bounds__(256) void k_maxscore(Ptrs P) {
    int b = blockIdx.y;
    int a = blockIdx.x * 256 + threadIdx.x;
    if (a >= NTOT) return;

    int l;
    if      (a < 15360) l = 0;
    else if (a < 19200) l = 1;
    else if (a < 20160) l = 2;
    else if (a < 20400) l = 3;
    else                l = 4;
    int r  = a - c_off[l];
    int HW = c_HW[l];

    const float* loc = P.p[4 * l + 3];
    float key = 0.f;
    float ls = sigf(loc[(size_t)b * HW + r]);
    if (ls >= 0.01f) {
        const float* cp = P.p[4 * l] + ((size_t)b * NUM_CLASSES) * HW + r;
        float m = -3.402823466e38f;
        #pragma unroll 8
        for (int c = 0; c < NUM_CLASSES; c++)
            m = fmaxf(m, cp[(size_t)c * HW]);
        key = dsigf(m);
    }
    g_key[(size_t)b * NTOT + a] = key;
}

// ---------------------------------------------------------------------------
// Kernel 2: per-image top-1000 by (key desc, idx asc). Radix-select threshold
// (warp-aggregated histogram atomics) then stable compaction + bitonic sort.
// ---------------------------------------------------------------------------
__global__ __launch_bounds__(1024) void k_select() {
    int b   = blockIdx.x;
    int tid = threadIdx.x;
    int lane = tid & 31, wid = tid >> 5;
    const unsigned* keys = reinterpret_cast<const unsigned*>(g_key) + (size_t)b * NTOT;

    __shared__ unsigned hist[256];
    __shared__ unsigned s_prefix;
    __shared__ int s_m;
    __shared__ unsigned long long sel[1024];
    __shared__ int warp_tot[32];
    __shared__ int warp_scan[32];
    __shared__ int s_fill;
    __shared__ int s_runeq;

    if (tid == 0) { s_prefix = 0u; s_m = TOPK; }
    __syncthreads();

    // --- 4-round radix select (8 bits per round) to find threshold T ---
    for (int round = 0; round < 4; round++) {
        int shift = 24 - 8 * round;
        unsigned kmask = (round == 0) ? 0u : (0xFFFFFFFFu << (32 - 8 * round));
        if (tid < 256) hist[tid] = 0u;
        __syncthreads();
        unsigned pfx = s_prefix;
        for (int i = tid; i < 20480; i += 1024) {   // padded uniform trip count
            bool v = i < NTOT;
            unsigned k = v ? keys[i] : 0u;
            bool act = v && ((k & kmask) == pfx);
            unsigned bin = (k >> shift) & 0xFFu;
            unsigned am = __ballot_sync(0xFFFFFFFFu, act);
            if (act) {
                unsigned peers = __match_any_sync(am, bin);
                if (lane == __ffs(peers) - 1)
                    atomicAdd(&hist[bin], (unsigned)__popc(peers));
            }
        }
        __syncthreads();
        if (tid == 0) {
            int m = s_m;
            unsigned cum = 0;
            for (int bin = 255; bin >= 0; bin--) {
                unsigned h = hist[bin];
                if (cum + h >= (unsigned)m) {
                    s_prefix = pfx | ((unsigned)bin << shift);
                    s_m = m - (int)cum;
                    break;
                }
                cum += h;
            }
        }
        __syncthreads();
    }
    unsigned T = s_prefix;
    int meq = s_m;                          // how many ==T to take (by index order)

    sel[tid] = 0ull;
    if (tid == 0) { s_fill = 0; s_runeq = 0; }
    __syncthreads();

    // --- compaction: all >T (order irrelevant, sorted later); first meq ==T ---
    for (int base = 0; base < NTOT; base += 1024) {
        int i = base + tid;
        bool valid = i < NTOT;
        unsigned k = valid ? keys[i] : 0u;
        bool gt = valid && (k > T);
        bool eq = valid && (k == T);
        if (gt) {
            int p = atomicAdd(&s_fill, 1);
            sel[p] = (((unsigned long long)k) << 32) |
                     (unsigned long long)(0xFFFFFFFFu - (unsigned)i);
        }
        unsigned bal = __ballot_sync(0xFFFFFFFFu, eq);
        if (lane == 0) warp_tot[wid] = __popc(bal);
        __syncthreads();
        if (wid == 0) {
            int v = warp_tot[lane];
            #pragma unroll
            for (int d = 1; d < 32; d <<= 1) {
                int n = __shfl_up_sync(0xFFFFFFFFu, v, d);
                if (lane >= d) v += n;
            }
            warp_scan[lane] = v;            // inclusive scan
        }
        __syncthreads();
        int wbase = (wid == 0) ? 0 : warp_scan[wid - 1];
        int rank = s_runeq + wbase + __popc(bal & ((1u << lane) - 1u));
        if (eq && rank < meq) {
            int p = atomicAdd(&s_fill, 1);
            sel[p] = (((unsigned long long)k) << 32) |
                     (unsigned long long)(0xFFFFFFFFu - (unsigned)i);
        }
        __syncthreads();
        if (tid == 0) s_runeq += warp_scan[31];
        __syncthreads();
    }

    // --- bitonic sort descending on composite (key desc, idx asc) ---
    for (int k2 = 2; k2 <= 1024; k2 <<= 1) {
        for (int j = k2 >> 1; j > 0; j >>= 1) {
            __syncthreads();
            int ixj = tid ^ j;
            if (ixj > tid) {
                unsigned long long va = sel[tid], vb = sel[ixj];
                bool up = ((tid & k2) == 0);
                if (up ? (va < vb) : (va > vb)) { sel[tid] = vb; sel[ixj] = va; }
            }
        }
    }
    __syncthreads();
    g_sel[b * 1024 + tid] = (int)(0xFFFFFFFFu - (unsigned)(sel[tid] & 0xFFFFFFFFull));
}

// ---------------------------------------------------------------------------
// Kernel 3: gather per-class scores (thresholded) + decode proposal box
// one warp per selected row
// ---------------------------------------------------------------------------
__global__ __launch_bounds__(256) void k_gather(Ptrs P) {
    int w = (blockIdx.x * 256 + threadIdx.x) >> 5;
    int lane = threadIdx.x & 31;
    if (w >= B_IMG * TOPK) return;
    int b = w / TOPK;
    int j = w - b * TOPK;
    int a = g_sel[b * 1024 + j];

    int l;
    if      (a < 15360) l = 0;
    else if (a < 19200) l = 1;
    else if (a < 20160) l = 2;
    else if (a < 20400) l = 3;
    else                l = 4;
    int r  = a - c_off[l];
    int HW = c_HW[l];
    int W  = c_W[l];
    int yi = r / W;
    int xi = r - yi * W;

    const float* cls = P.p[4 * l + 0];
    const float* bb  = P.p[4 * l + 1];
    const float* shp = P.p[4 * l + 2];
    const float* loc = P.p[4 * l + 3];

    float maskf = (sigf(loc[(size_t)b * HW + r]) >= 0.01f) ? 1.f : 0.f;

    for (int c = lane; c < NUM_CLASSES; c += 32) {
        float v = cls[((size_t)b * NUM_CLASSES + c) * HW + r];
        float s = maskf * dsigf(v);
        g_sc[((size_t)b * NUM_CLASSES + c) * 1024 + j] = (s > 0.05f) ? s : 0.f;
    }

    if (lane == 0) {
        float st = c_stride[l];
        float xx = (float)xi * st, yy = (float)yi * st;
        float pw = 4.f * st;
        // guided anchor (delta2bbox with [0,0,dw,dh])
        float dw = clampf(shp[((size_t)b * 2 + 0) * HW + r], -MAX_RATIO_ANCHOR, MAX_RATIO_ANCHOR);
        float dh = clampf(shp[((size_t)b * 2 + 1) * HW + r], -MAX_RATIO_ANCHOR, MAX_RATIO_ANCHOR);
        float aw = pw * expf(dw);
        float ah = pw * expf(dh);
        float ax1 = xx - 0.5f * aw, ay1 = yy - 0.5f * ah;
        float ax2 = xx + 0.5f * aw, ay2 = yy + 0.5f * ah;
        // bbox decode (delta2bbox, clipped to image)
        float px = (ax1 + ax2) * 0.5f, py = (ay1 + ay2) * 0.5f;
        float w2 = ax2 - ax1,          h2 = ay2 - ay1;
        float dx  = bb[((size_t)b * 4 + 0) * HW + r];
        float dy  = bb[((size_t)b * 4 + 1) * HW + r];
        float dw2 = clampf(bb[((size_t)b * 4 + 2) * HW + r], -MAX_RATIO_BBOX, MAX_RATIO_BBOX);
        float dh2 = clampf(bb[((size_t)b * 4 + 3) * HW + r], -MAX_RATIO_BBOX, MAX_RATIO_BBOX);
        float gx = px + w2 * dx;
        float gy = py + h2 * dy;
        float gw = w2 * expf(dw2);
        float gh = h2 * expf(dh2);
        float x1 = clampf(gx - 0.5f * gw, 0.f, IMG_W);
        float y1 = clampf(gy - 0.5f * gh, 0.f, IMG_H);
        float x2 = clampf(gx + 0.5f * gw, 0.f, IMG_W);
        float y2 = clampf(gy + 0.5f * gh, 0.f, IMG_H);
        g_boxes[b * 1024 + j] = make_float4(x1, y1, x2, y2);
    }
}

// ---------------------------------------------------------------------------
// Kernel 4a: independent per-class greedy NMS (no cross-class suppression:
// class offsets 4096 > image extent make cross-class IoU exactly 0).
// One warp per (image, class); scores live in registers, boxes in smem.
// A pick that survives its own suppression (degenerate/zero-area box) is
// "sticky": the reference scan re-picks it forever -> record & stop.
// ---------------------------------------------------------------------------
__global__ __launch_bounds__(256) void k_classnms() {
    int b    = blockIdx.y;
    int cg   = blockIdx.x;                  // 0..9
    int wid  = threadIdx.x >> 5;
    int lane = threadIdx.x & 31;
    int c    = cg * 8 + wid;

    __shared__ float4 sbox[TOPK];
    for (int i = threadIdx.x; i < TOPK; i += 256)
        sbox[i] = g_boxes[b * 1024 + i];
    __syncthreads();

    // per-lane register-resident scores: j = lane + 32*k
    float s[32];
    const float* sp = g_sc + ((size_t)b * NUM_CLASSES + c) * 1024;
    #pragma unroll
    for (int k = 0; k < 32; k++) {
        int j = lane + 32 * k;
        s[k] = (j < TOPK) ? sp[j] : 0.f;
    }

    float offc = CLS_OFFSET * (float)c;
    int cnt = 0, sticky = 0;
    float*          ps = g_pick_s + (size_t)(b * NUM_CLASSES + c) * MAX_PER_IMG;
    unsigned short* pr = g_pick_r + (size_t)(b * NUM_CLASSES + c) * MAX_PER_IMG;

    for (int t = 0; t < MAX_PER_IMG; t++) {
        // argmax by (score desc, j asc)
        unsigned long long best = 0ull;
        #pragma unroll
        for (int k = 0; k < 32; k++) {
            if (s[k] > 0.f) {
                unsigned long long comp =
                    ((unsigned long long)__float_as_uint(s[k]) << 32)
                    | (unsigned long long)(0xFFFFFFFFu - (unsigned)(lane + 32 * k));
                if (comp > best) best = comp;
            }
        }
        #pragma unroll
        for (int d = 16; d; d >>= 1) {
            unsigned long long o = __shfl_xor_sync(0xFFFFFFFFu, best, d);
            if (o > best) best = o;
        }
        if (best == 0ull) break;                       // class exhausted
        int   j  = (int)(0xFFFFFFFFu - (unsigned)(best & 0xFFFFFFFFull));
        float sc = __uint_as_float((unsigned)(best >> 32));

        if (lane == 0) { ps[cnt] = sc; pr[cnt] = (unsigned short)j; }
        cnt++;

        // suppression over this class (offset boxes — matches reference rounding)
        float4 pb = sbox[j];
        float px1 = pb.x + offc, py1 = pb.y + offc;
        float px2 = pb.z + offc, py2 = pb.w + offc;
        float a1 = (px2 - px1) * (py2 - py1);

        bool surv = false;
        #pragma unroll
        for (int k = 0; k < 32; k++) {
            int jj = lane + 32 * k;
            if (s[k] > 0.f) {
                float4 q = sbox[jj];
                float qx1 = q.x + offc, qy1 = q.y + offc;
                float qx2 = q.z + offc, qy2 = q.w + offc;
                float ltx = fmaxf(px1, qx1), lty = fmaxf(py1, qy1);
                float rbx = fminf(px2, qx2), rby = fminf(py2, qy2);
                float ww = fmaxf(rbx - ltx, 0.f);
                float hh = fmaxf(rby - lty, 0.f);
                float inter = ww * hh;
                float a2 = (qx2 - qx1) * (qy2 - qy1);
                float iou = inter / (a1 + a2 - inter + 1e-6f);
                if (iou > 0.5f) s[k] = 0.f;
            }
            if (jj == j) surv = (s[k] > 0.f);
        }
        if (__ballot_sync(0xFFFFFFFFu, surv)) { sticky = 1; break; }
    }

    if (lane == 0) {
        g_pick_cnt[b * NUM_CLASSES + c] = cnt;
        g_pick_stk[b * NUM_CLASSES + c] = sticky;
    }
}

// ---------------------------------------------------------------------------
// Kernel 4b: per-image 100-step merge of 80 sorted pick lists.
// Tie-break = flattened key r*80+c asc (jax argmax over [N*C]).
// Sticky head never advances (reference re-picks it forever).
// ---------------------------------------------------------------------------
__global__ __launch_bounds__(256) void k_merge(float* __restrict__ out) {
    int b = blockIdx.x;
    int tid = threadIdx.x;

    __shared__ float          s_ps[NUM_CLASSES * MAX_PER_IMG];
    __shared__ unsigned short s_pr[NUM_CLASSES * MAX_PER_IMG];
    __shared__ int            s_cnt[NUM_CLASSES];
    __shared__ int            s_stk[NUM_CLASSES];

    for (int i = tid; i < NUM_CLASSES * MAX_PER_IMG; i += 256) {
        s_ps[i] = g_pick_s[(size_t)b * NUM_CLASSES * MAX_PER_IMG + i];
        s_pr[i] = g_pick_r[(size_t)b * NUM_CLASSES * MAX_PER_IMG + i];
    }
    if (tid < NUM_CLASSES) {
        s_cnt[tid] = g_pick_cnt[b * NUM_CLASSES + tid];
        s_stk[tid] = g_pick_stk[b * NUM_CLASSES + tid];
    }
    __syncthreads();
    if (tid >= 32) return;
    int lane = tid;

    float* outB = out + 8;
    float* outS = outB + B_IMG * MAX_PER_IMG * 4;
    float* outC = outS + B_IMG * MAX_PER_IMG;

    // lane owns classes lane, lane+32, lane+64 (lane<16)
    int p0 = 0, p1 = 0, p2 = 0;
    int ndet = 0;

    for (int t = 0; t < MAX_PER_IMG; t++) {
        unsigned long long best = 0ull;
        {
            int c = lane;
            if (p0 < s_cnt[c]) {
                unsigned key = (unsigned)s_pr[c * MAX_PER_IMG + p0] * 80u + (unsigned)c;
                unsigned long long comp =
                    ((unsigned long long)__float_as_uint(s_ps[c * MAX_PER_IMG + p0]) << 32)
                    | (unsigned long long)(0xFFFFFFFFu - key);
                if (comp > best) best = comp;
            }
        }
        {
            int c = lane + 32;
            if (p1 < s_cnt[c]) {
                unsigned key = (unsigned)s_pr[c * MAX_PER_IMG + p1] * 80u + (unsigned)c;
                unsigned long long comp =
                    ((unsigned long long)__float_as_uint(s_ps[c * MAX_PER_IMG + p1]) << 32)
                    | (unsigned long long)(0xFFFFFFFFu - key);
                if (comp > best) best = comp;
            }
        }
        if (lane < 16) {
            int c = lane + 64;
            if (p2 < s_cnt[c]) {
                unsigned key = (unsigned)s_pr[c * MAX_PER_IMG + p2] * 80u + (unsigned)c;
                unsigned long long comp =
                    ((unsigned long long)__float_as_uint(s_ps[c * MAX_PER_IMG + p2]) << 32)
                    | (unsigned long long)(0xFFFFFFFFu - key);
                if (comp > best) best = comp;
            }
        }
        #pragma unroll
        for (int d = 16; d; d >>= 1) {
            unsigned long long o = __shfl_xor_sync(0xFFFFFFFFu, best, d);
            if (o > best) best = o;
        }

        if (best == 0ull) {
            // everything exhausted: remaining slots -> zeros, cls=-1
            for (int tt = t + lane; tt < MAX_PER_IMG; tt += 32) {
                int o = b * MAX_PER_IMG + tt;
                outB[o * 4 + 0] = 0.f; outB[o * 4 + 1] = 0.f;
                outB[o * 4 + 2] = 0.f; outB[o * 4 + 3] = 0.f;
                outS[o] = 0.f;
                outC[o] = -1.f;
            }
            break;
        }

        unsigned key = 0xFFFFFFFFu - (unsigned)(best & 0xFFFFFFFFull);
        int c = (int)(key % 80u);
        int r = (int)(key / 80u);
        float sc = __uint_as_float((unsigned)(best >> 32));

        if (lane == 0) {
            float4 bx = g_boxes[b * 1024 + r];
            int o = b * MAX_PER_IMG + t;
            outB[o * 4 + 0] = bx.x;
            outB[o * 4 + 1] = bx.y;
            outB[o * 4 + 2] = bx.z;
            outB[o * 4 + 3] = bx.w;
            outS[o] = sc;
            outC[o] = (float)c;
        }
        ndet++;

        // advance owner (unless sticky at tail: reference re-picks it forever)
        if (c == lane) {
            if (!(s_stk[c] && p0 == s_cnt[c] - 1)) p0++;
        } else if (c == lane + 32) {
            if (!(s_stk[c] && p1 == s_cnt[c] - 1)) p1++;
        } else if (lane < 16 && c == lane + 64) {
            if (!(s_stk[c] && p2 == s_cnt[c] - 1)) p2++;
        }
    }

    if (lane == 0) out[b] = (float)ndet;
}

// ---------------------------------------------------------------------------
// Launch
// ---------------------------------------------------------------------------
extern "C" void kernel_launch(void* const* d_in, const int* in_sizes, int n_in,
                              void* d_out, int out_size) {
    (void)in_sizes; (void)n_in; (void)out_size;
    Ptrs P;
    for (int i = 0; i < 20; i++) P.p[i] = (const float*)d_in[i];
    float* out = (float*)d_out;

    dim3 g1((NTOT + 255) / 256, B_IMG);
    k_maxscore<<<g1, 256>>>(P);
    k_select<<<B_IMG, 1024>>>();
    k_gather<<<(B_IMG * TOPK * 32 + 255) / 256, 256>>>(P);
    k_classnms<<<dim3(10, B_IMG), 256>>>();
    k_merge<<<B_IMG, 256>>>(out);
}

// round 3
// speedup vs baseline: 4.4171x; 4.4171x over previous
#include <cuda_runtime.h>
#include <cstdint>

// ---------------------------------------------------------------------------
// Problem constants
// ---------------------------------------------------------------------------
#define NUM_CLASSES 80
#define B_IMG 8
#define NTOT 20460            // total anchors per image across 5 levels
#define TOPK 1000
#define MAX_PER_IMG 100
#define K_CAP 16              // phase-A per-class pick cap
#define IMG_H 768.0f
#define IMG_W 1280.0f
#define CLS_OFFSET 4096.0f
#define MAX_RATIO_ANCHOR 13.815510557964274f   // |log(1e-6)|
#define MAX_RATIO_BBOX   4.135166556742356f    // |log(16/1000)|

__device__ __constant__ int   c_HW[5]     = {15360, 3840, 960, 240, 60};
__device__ __constant__ int   c_W[5]      = {160, 80, 40, 20, 10};
__device__ __constant__ int   c_off[5]    = {0, 15360, 19200, 20160, 20400};
__device__ __constant__ float c_stride[5] = {8.f, 16.f, 32.f, 64.f, 128.f};

// ---------------------------------------------------------------------------
// Scratch (device globals; no runtime allocation allowed)
// ---------------------------------------------------------------------------
__device__ float  g_key[B_IMG * NTOT];          // per-anchor masked max score
__device__ int    g_sel[B_IMG * 1024];          // selected anchor ids (sorted)
__device__ float  g_sc[B_IMG * NUM_CLASSES * 1024]; // class-major scores, thresholded
__device__ float4 g_boxes[B_IMG * 1024];        // decoded proposals

// per-class NMS pick lists
__device__ float          g_pick_s[B_IMG * NUM_CLASSES * MAX_PER_IMG];
__device__ unsigned short g_pick_r[B_IMG * NUM_CLASSES * MAX_PER_IMG];
__device__ int            g_pick_cnt[B_IMG * NUM_CLASSES];
__device__ int            g_pick_stk[B_IMG * NUM_CLASSES];
__device__ int            g_redo;

struct Ptrs { const float* p[20]; };

// ---------------------------------------------------------------------------
// Numerics matching jax
// ---------------------------------------------------------------------------
__device__ __forceinline__ float sigf(float x) {
    if (x >= 0.f) return 1.f / (1.f + expf(-x));
    float e = expf(x);
    return e / (1.f + e);
}
__device__ __forceinline__ float dsigf(float x) {
    float s = sigf(x);              // s in (0,1) -> non-negative branch
    return 1.f / (1.f + expf(-s));
}
__device__ __forceinline__ float clampf(float v, float lo, float hi) {
    return fminf(fmaxf(v, lo), hi);
}

// ---------------------------------------------------------------------------
// Kernel 1: per-anchor masked max-class score (key for top-k)
// ---------------------------------------------------------------------------
__global__ __launch_bounds__(256) void k_maxscore(Ptrs P) {
    if (blockIdx.x == 0 && blockIdx.y == 0 && threadIdx.x == 0) g_redo = 0;
    int b = blockIdx.y;
    int a = blockIdx.x * 256 + threadIdx.x;
    if (a >= NTOT) return;

    int l;
    if      (a < 15360) l = 0;
    else if (a < 19200) l = 1;
    else if (a < 20160) l = 2;
    else if (a < 20400) l = 3;
    else                l = 4;
    int r  = a - c_off[l];
    int HW = c_HW[l];

    const float* loc = P.p[4 * l + 3];
    float key = 0.f;
    float ls = sigf(loc[(size_t)b * HW + r]);
    if (ls >= 0.01f) {
        const float* cp = P.p[4 * l] + ((size_t)b * NUM_CLASSES) * HW + r;
        float m = -3.402823466e38f;
        #pragma unroll 8
        for (int c = 0; c < NUM_CLASSES; c++)
            m = fmaxf(m, cp[(size_t)c * HW]);
        key = dsigf(m);
    }
    g_key[(size_t)b * NTOT + a] = key;
}

// ---------------------------------------------------------------------------
// Kernel 2: per-image top-1000 by (key desc, idx asc). Radix-select threshold
// (warp-aggregated histogram atomics) then stable compaction + bitonic sort.
// ---------------------------------------------------------------------------
__global__ __launch_bounds__(1024) void k_select() {
    int b   = blockIdx.x;
    int tid = threadIdx.x;
    int lane = tid & 31, wid = tid >> 5;
    const unsigned* keys = reinterpret_cast<const unsigned*>(g_key) + (size_t)b * NTOT;

    __shared__ unsigned hist[256];
    __shared__ unsigned s_prefix;
    __shared__ int s_m;
    __shared__ unsigned long long sel[1024];
    __shared__ int warp_tot[32];
    __shared__ int warp_scan[32];
    __shared__ int s_fill;
    __shared__ int s_runeq;

    if (tid == 0) { s_prefix = 0u; s_m = TOPK; }
    __syncthreads();

    // --- 4-round radix select (8 bits per round) to find threshold T ---
    for (int round = 0; round < 4; round++) {
        int shift = 24 - 8 * round;
        unsigned kmask = (round == 0) ? 0u : (0xFFFFFFFFu << (32 - 8 * round));
        if (tid < 256) hist[tid] = 0u;
        __syncthreads();
        unsigned pfx = s_prefix;
        for (int i = tid; i < 20480; i += 1024) {   // padded uniform trip count
            bool v = i < NTOT;
            unsigned k = v ? keys[i] : 0u;
            bool act = v && ((k & kmask) == pfx);
            unsigned bin = (k >> shift) & 0xFFu;
            unsigned am = __ballot_sync(0xFFFFFFFFu, act);
            if (act) {
                unsigned peers = __match_any_sync(am, bin);
                if (lane == __ffs(peers) - 1)
                    atomicAdd(&hist[bin], (unsigned)__popc(peers));
            }
        }
        __syncthreads();
        if (tid == 0) {
            int m = s_m;
            unsigned cum = 0;
            for (int bin = 255; bin >= 0; bin--) {
                unsigned h = hist[bin];
                if (cum + h >= (unsigned)m) {
                    s_prefix = pfx | ((unsigned)bin << shift);
                    s_m = m - (int)cum;
                    break;
                }
                cum += h;
            }
        }
        __syncthreads();
    }
    unsigned T = s_prefix;
    int meq = s_m;                          // how many ==T to take (by index order)

    sel[tid] = 0ull;
    if (tid == 0) { s_fill = 0; s_runeq = 0; }
    __syncthreads();

    // --- compaction: all >T (order irrelevant, sorted later); first meq ==T ---
    for (int base = 0; base < NTOT; base += 1024) {
        int i = base + tid;
        bool valid = i < NTOT;
        unsigned k = valid ? keys[i] : 0u;
        bool gt = valid && (k > T);
        bool eq = valid && (k == T);
        if (gt) {
            int p = atomicAdd(&s_fill, 1);
            sel[p] = (((unsigned long long)k) << 32) |
                     (unsigned long long)(0xFFFFFFFFu - (unsigned)i);
        }
        unsigned bal = __ballot_sync(0xFFFFFFFFu, eq);
        if (lane == 0) warp_tot[wid] = __popc(bal);
        __syncthreads();
        if (wid == 0) {
            int v = warp_tot[lane];
            #pragma unroll
            for (int d = 1; d < 32; d <<= 1) {
                int n = __shfl_up_sync(0xFFFFFFFFu, v, d);
                if (lane >= d) v += n;
            }
            warp_scan[lane] = v;            // inclusive scan
        }
        __syncthreads();
        int wbase = (wid == 0) ? 0 : warp_scan[wid - 1];
        int rank = s_runeq + wbase + __popc(bal & ((1u << lane) - 1u));
        if (eq && rank < meq) {
            int p = atomicAdd(&s_fill, 1);
            sel[p] = (((unsigned long long)k) << 32) |
                     (unsigned long long)(0xFFFFFFFFu - (unsigned)i);
        }
        __syncthreads();
        if (tid == 0) s_runeq += warp_scan[31];
        __syncthreads();
    }

    // --- bitonic sort descending on composite (key desc, idx asc) ---
    for (int k2 = 2; k2 <= 1024; k2 <<= 1) {
        for (int j = k2 >> 1; j > 0; j >>= 1) {
            __syncthreads();
            int ixj = tid ^ j;
            if (ixj > tid) {
                unsigned long long va = sel[tid], vb = sel[ixj];
                bool up = ((tid & k2) == 0);
                if (up ? (va < vb) : (va > vb)) { sel[tid] = vb; sel[ixj] = va; }
            }
        }
    }
    __syncthreads();
    g_sel[b * 1024 + tid] = (int)(0xFFFFFFFFu - (unsigned)(sel[tid] & 0xFFFFFFFFull));
}

// ---------------------------------------------------------------------------
// Kernel 3: gather per-class scores (thresholded) + decode proposal box
// one warp per selected row
// ---------------------------------------------------------------------------
__global__ __launch_bounds__(256) void k_gather(Ptrs P) {
    int w = (blockIdx.x * 256 + threadIdx.x) >> 5;
    int lane = threadIdx.x & 31;
    if (w >= B_IMG * TOPK) return;
    int b = w / TOPK;
    int j = w - b * TOPK;
    int a = g_sel[b * 1024 + j];

    int l;
    if      (a < 15360) l = 0;
    else if (a < 19200) l = 1;
    else if (a < 20160) l = 2;
    else if (a < 20400) l = 3;
    else                l = 4;
    int r  = a - c_off[l];
    int HW = c_HW[l];
    int W  = c_W[l];
    int yi = r / W;
    int xi = r - yi * W;

    const float* cls = P.p[4 * l + 0];
    const float* bb  = P.p[4 * l + 1];
    const float* shp = P.p[4 * l + 2];
    const float* loc = P.p[4 * l + 3];

    float maskf = (sigf(loc[(size_t)b * HW + r]) >= 0.01f) ? 1.f : 0.f;

    for (int c = lane; c < NUM_CLASSES; c += 32) {
        float v = cls[((size_t)b * NUM_CLASSES + c) * HW + r];
        float s = maskf * dsigf(v);
        g_sc[((size_t)b * NUM_CLASSES + c) * 1024 + j] = (s > 0.05f) ? s : 0.f;
    }

    if (lane == 0) {
        float st = c_stride[l];
        float xx = (float)xi * st, yy = (float)yi * st;
        float pw = 4.f * st;
        // guided anchor (delta2bbox with [0,0,dw,dh])
        float dw = clampf(shp[((size_t)b * 2 + 0) * HW + r], -MAX_RATIO_ANCHOR, MAX_RATIO_ANCHOR);
        float dh = clampf(shp[((size_t)b * 2 + 1) * HW + r], -MAX_RATIO_ANCHOR, MAX_RATIO_ANCHOR);
        float aw = pw * expf(dw);
        float ah = pw * expf(dh);
        float ax1 = xx - 0.5f * aw, ay1 = yy - 0.5f * ah;
        float ax2 = xx + 0.5f * aw, ay2 = yy + 0.5f * ah;
        // bbox decode (delta2bbox, clipped to image)
        float px = (ax1 + ax2) * 0.5f, py = (ay1 + ay2) * 0.5f;
        float w2 = ax2 - ax1,          h2 = ay2 - ay1;
        float dx  = bb[((size_t)b * 4 + 0) * HW + r];
        float dy  = bb[((size_t)b * 4 + 1) * HW + r];
        float dw2 = clampf(bb[((size_t)b * 4 + 2) * HW + r], -MAX_RATIO_BBOX, MAX_RATIO_BBOX);
        float dh2 = clampf(bb[((size_t)b * 4 + 3) * HW + r], -MAX_RATIO_BBOX, MAX_RATIO_BBOX);
        float gx = px + w2 * dx;
        float gy = py + h2 * dy;
        float gw = w2 * expf(dw2);
        float gh = h2 * expf(dh2);
        float x1 = clampf(gx - 0.5f * gw, 0.f, IMG_W);
        float y1 = clampf(gy - 0.5f * gh, 0.f, IMG_H);
        float x2 = clampf(gx + 0.5f * gw, 0.f, IMG_W);
        float y2 = clampf(gy + 0.5f * gh, 0.f, IMG_H);
        g_boxes[b * 1024 + j] = make_float4(x1, y1, x2, y2);
    }
}

// ---------------------------------------------------------------------------
// Kernel 4: per-class greedy NMS, capped pick list. One 128-thread block per
// (image, class). Cross-class suppression is impossible (class offsets 4096 >
// image extent make cross-class IoU exactly 0), so classes are independent.
// A pick that survives its own suppression (degenerate zero-area box) is
// "sticky": reference re-picks it forever -> flag & stop.
// redo_pass: only recompute (at cap=100) classes left "open" by phase A,
// and only when phase-B merge flagged g_redo.
// ---------------------------------------------------------------------------
__global__ __launch_bounds__(128) void k_classnms(int cap, int redo_pass) {
    int c = blockIdx.x;
    int b = blockIdx.y;
    int idx = b * NUM_CLASSES + c;
    if (redo_pass) {
        if (g_redo == 0) return;
        if (!(g_pick_cnt[idx] == K_CAP && g_pick_stk[idx] == 0)) return; // closed
    }
    int tid = threadIdx.x;
    int lane = tid & 31, wid = tid >> 5;

    __shared__ float4 sbox[TOPK];
    __shared__ unsigned long long warpbest[4];
    __shared__ int s_sticky;

    for (int i = tid; i < TOPK; i += 128)
        sbox[i] = g_boxes[b * 1024 + i];
    if (tid == 0) s_sticky = 0;

    // register-resident scores: thread owns j = tid + 128*k
    float s[8];
    const float* sp = g_sc + ((size_t)idx) * 1024;
    #pragma unroll
    for (int k = 0; k < 8; k++) {
        int j = tid + 128 * k;
        s[k] = (j < TOPK) ? sp[j] : 0.f;
    }
    __syncthreads();

    float offc = CLS_OFFSET * (float)c;
    int cnt = 0;
    float*          ps = g_pick_s + (size_t)idx * MAX_PER_IMG;
    unsigned short* pr = g_pick_r + (size_t)idx * MAX_PER_IMG;

    for (int t = 0; t < cap; t++) {
        // local argmax by (score desc, j asc)
        unsigned long long best = 0ull;
        #pragma unroll
        for (int k = 0; k < 8; k++) {
            if (s[k] > 0.f) {
                unsigned long long comp =
                    ((unsigned long long)__float_as_uint(s[k]) << 32)
                    | (unsigned long long)(0xFFFFFFFFu - (unsigned)(tid + 128 * k));
                if (comp > best) best = comp;
            }
        }
        #pragma unroll
        for (int d = 16; d; d >>= 1) {
            unsigned long long o = __shfl_xor_sync(0xFFFFFFFFu, best, d);
            if (o > best) best = o;
        }
        if (lane == 0) warpbest[wid] = best;
        __syncthreads();                           // (1) warpbest + s_sticky visible
        if (s_sticky) break;                       // previous pick was sticky
        unsigned long long b0 = warpbest[0];
        if (warpbest[1] > b0) b0 = warpbest[1];
        if (warpbest[2] > b0) b0 = warpbest[2];
        if (warpbest[3] > b0) b0 = warpbest[3];
        if (b0 == 0ull) break;                     // class exhausted

        int   j  = (int)(0xFFFFFFFFu - (unsigned)(b0 & 0xFFFFFFFFull));
        float sc = __uint_as_float((unsigned)(b0 >> 32));
        if (tid == 0) { ps[cnt] = sc; pr[cnt] = (unsigned short)j; }
        cnt++;

        // suppression (offset boxes — matches reference rounding exactly)
        float4 pb = sbox[j];
        float px1 = pb.x + offc, py1 = pb.y + offc;
        float px2 = pb.z + offc, py2 = pb.w + offc;
        float a1 = (px2 - px1) * (py2 - py1);

        #pragma unroll
        for (int k = 0; k < 8; k++) {
            int jj = tid + 128 * k;
            if (s[k] > 0.f) {
                float4 q = sbox[jj];
                float qx1 = q.x + offc, qy1 = q.y + offc;
                float qx2 = q.z + offc, qy2 = q.w + offc;
                float ltx = fmaxf(px1, qx1), lty = fmaxf(py1, qy1);
                float rbx = fminf(px2, qx2), rby = fminf(py2, qy2);
                float ww = fmaxf(rbx - ltx, 0.f);
                float hh = fmaxf(rby - lty, 0.f);
                float inter = ww * hh;
                float a2 = (qx2 - qx1) * (qy2 - qy1);
                float iou = inter / (a1 + a2 - inter + 1e-6f);
                if (iou > 0.5f) s[k] = 0.f;
            }
            if (jj == j && s[k] > 0.f) s_sticky = 1;   // pick survived itself
        }
        __syncthreads();                           // (2) suppression + flag done
    }

    if (tid == 0) {
        g_pick_cnt[idx] = cnt;
        g_pick_stk[idx] = s_sticky;
    }
}

// ---------------------------------------------------------------------------
// Kernel 5: per-image merge of 80 sorted pick lists (100 steps).
// Tie-break = flattened key r*80+c asc (jax argmax over [N*C]).
// Sticky head never advances. In the validation pass (final=0), a class that
// hit cap K_CAP un-exhausted is "open": if its last-known score could beat or
// tie the winner, flag g_redo and abort (phases C/D fix it up).
// ---------------------------------------------------------------------------
__global__ __launch_bounds__(128) void k_merge(float* __restrict__ out, int final_pass) {
    if (final_pass && g_redo == 0) return;   // phase-B output already valid
    int b = blockIdx.x;
    int tid = threadIdx.x;
    int lane = tid & 31;

    __shared__ float          s_ps[NUM_CLASSES * MAX_PER_IMG];
    __shared__ unsigned short s_pr[NUM_CLASSES * MAX_PER_IMG];
    __shared__ int            s_cnt[NUM_CLASSES];
    __shared__ int            s_stk[NUM_CLASSES];
    __shared__ int            s_open[NUM_CLASSES];

    if (tid < NUM_CLASSES) {
        int cnt = g_pick_cnt[b * NUM_CLASSES + tid];
        int stk = g_pick_stk[b * NUM_CLASSES + tid];
        s_cnt[tid] = cnt;
        s_stk[tid] = stk;
        s_open[tid] = (!final_pass && cnt == K_CAP && stk == 0) ? 1 : 0;
    }
    __syncthreads();
    for (int c = tid >> 2; c < NUM_CLASSES; c += 32) {
        int cnt = s_cnt[c];
        for (int p = tid & 3; p < cnt; p += 4) {
            s_ps[c * MAX_PER_IMG + p] = g_pick_s[((size_t)(b * NUM_CLASSES + c)) * MAX_PER_IMG + p];
            s_pr[c * MAX_PER_IMG + p] = g_pick_r[((size_t)(b * NUM_CLASSES + c)) * MAX_PER_IMG + p];
        }
    }
    __syncthreads();
    if (tid >= 32) return;

    float* outB = out + 8;
    float* outS = outB + B_IMG * MAX_PER_IMG * 4;
    float* outC = outS + B_IMG * MAX_PER_IMG;

    // lane owns classes lane, lane+32, lane+64(<80)
    int p[3] = {0, 0, 0};
    int ndet = 0;
    bool valid = true;

    for (int t = 0; t < MAX_PER_IMG; t++) {
        unsigned long long best = 0ull;
        unsigned boundbits = 0u;
        #pragma unroll
        for (int q = 0; q < 3; q++) {
            int c = lane + 32 * q;
            if (c < NUM_CLASSES) {
                int pp = p[q], cnt = s_cnt[c];
                if (pp < cnt) {
                    unsigned key = (unsigned)s_pr[c * MAX_PER_IMG + pp] * 80u + (unsigned)c;
                    unsigned long long comp =
                        ((unsigned long long)__float_as_uint(s_ps[c * MAX_PER_IMG + pp]) << 32)
                        | (unsigned long long)(0xFFFFFFFFu - key);
                    if (comp > best) best = comp;
                } else if (s_open[c]) {
                    unsigned bb2 = __float_as_uint(s_ps[c * MAX_PER_IMG + cnt - 1]);
                    if (bb2 > boundbits) boundbits = bb2;
                }
            }
        }
        #pragma unroll
        for (int d = 16; d; d >>= 1) {
            unsigned long long o = __shfl_xor_sync(0xFFFFFFFFu, best, d);
            if (o > best) best = o;
            unsigned ob = __shfl_xor_sync(0xFFFFFFFFu, boundbits, d);
            if (ob > boundbits) boundbits = ob;
        }

        // validation: an open class might hold a better (or tied) future pick
        if (boundbits != 0u &&
            (best == 0ull || boundbits >= (unsigned)(best >> 32))) {
            if (lane == 0) g_redo = 1;
            valid = false;
            break;
        }

        if (best == 0ull) {
            for (int tt = t + lane; tt < MAX_PER_IMG; tt += 32) {
                int o = b * MAX_PER_IMG + tt;
                outB[o * 4 + 0] = 0.f; outB[o * 4 + 1] = 0.f;
                outB[o * 4 + 2] = 0.f; outB[o * 4 + 3] = 0.f;
                outS[o] = 0.f;
                outC[o] = -1.f;
            }
            break;
        }

        unsigned key = 0xFFFFFFFFu - (unsigned)(best & 0xFFFFFFFFull);
        int c = (int)(key % 80u);
        int r = (int)(key / 80u);
        float sc = __uint_as_float((unsigned)(best >> 32));

        if (lane == 0) {
            float4 bx = g_boxes[b * 1024 + r];
            int o = b * MAX_PER_IMG + t;
            outB[o * 4 + 0] = bx.x;
            outB[o * 4 + 1] = bx.y;
            outB[o * 4 + 2] = bx.z;
            outB[o * 4 + 3] = bx.w;
            outS[o] = sc;
            outC[o] = (float)c;
        }
        ndet++;

        // advance owner (unless sticky at tail: reference re-picks forever)
        int q = -1;
        if (c == lane) q = 0;
        else if (c == lane + 32) q = 1;
        else if (c == lane + 64) q = 2;
        if (q >= 0) {
            if (!(s_stk[c] && p[q] == s_cnt[c] - 1)) p[q]++;
        }
    }

    if (valid && lane == 0) out[b] = (float)ndet;
}

// ---------------------------------------------------------------------------
// Launch
// ---------------------------------------------------------------------------
extern "C" void kernel_launch(void* const* d_in, const int* in_sizes, int n_in,
                              void* d_out, int out_size) {
    (void)in_sizes; (void)n_in; (void)out_size;
    Ptrs P;
    for (int i = 0; i < 20; i++) P.p[i] = (const float*)d_in[i];
    float* out = (float*)d_out;

    dim3 g1((NTOT + 255) / 256, B_IMG);
    k_maxscore<<<g1, 256>>>(P);
    k_select<<<B_IMG, 1024>>>();
    k_gather<<<(B_IMG * TOPK * 32 + 255) / 256, 256>>>(P);
    k_classnms<<<dim3(NUM_CLASSES, B_IMG), 128>>>(K_CAP, 0);     // phase A
    k_merge<<<B_IMG, 128>>>(out, 0);                             // phase B
    k_classnms<<<dim3(NUM_CLASSES, B_IMG), 128>>>(MAX_PER_IMG, 1); // phase C
    k_merge<<<B_IMG, 128>>>(out, 1);                             // phase D
}

// round 4
// speedup vs baseline: 5.4491x; 1.2336x over previous
#include <cuda_runtime.h>
#include <cstdint>

// ---------------------------------------------------------------------------
// Problem constants
// ---------------------------------------------------------------------------
#define NUM_CLASSES 80
#define B_IMG 8
#define NTOT 20460            // total anchors per image across 5 levels
#define TOPK 1000
#define MAX_PER_IMG 100
#define K_CAP 16              // phase-A per-class pick cap
#define IMG_H 768.0f
#define IMG_W 1280.0f
#define CLS_OFFSET 4096.0f
#define MAX_RATIO_ANCHOR 13.815510557964274f   // |log(1e-6)|
#define MAX_RATIO_BBOX   4.135166556742356f    // |log(16/1000)|

__device__ __constant__ int   c_HW[5]     = {15360, 3840, 960, 240, 60};
__device__ __constant__ int   c_W[5]      = {160, 80, 40, 20, 10};
__device__ __constant__ int   c_off[5]    = {0, 15360, 19200, 20160, 20400};
__device__ __constant__ float c_stride[5] = {8.f, 16.f, 32.f, 64.f, 128.f};

// ---------------------------------------------------------------------------
// Scratch (device globals; no runtime allocation allowed)
// ---------------------------------------------------------------------------
__device__ float  g_key[B_IMG * NTOT];          // per-anchor masked max score
__device__ int    g_sel[B_IMG * 1024];          // selected anchor ids (sorted)
__device__ float  g_sc[B_IMG * NUM_CLASSES * 1024]; // class-major scores, thresholded
__device__ float4 g_boxes[B_IMG * 1024];        // decoded proposals

// per-class NMS pick lists
__device__ float          g_pick_s[B_IMG * NUM_CLASSES * MAX_PER_IMG];
__device__ unsigned short g_pick_r[B_IMG * NUM_CLASSES * MAX_PER_IMG];
__device__ int            g_pick_cnt[B_IMG * NUM_CLASSES];
__device__ int            g_pick_stk[B_IMG * NUM_CLASSES];
__device__ int            g_redo;

struct Ptrs { const float* p[20]; };

// ---------------------------------------------------------------------------
// Numerics matching jax
// ---------------------------------------------------------------------------
__device__ __forceinline__ float sigf(float x) {
    if (x >= 0.f) return 1.f / (1.f + expf(-x));
    float e = expf(x);
    return e / (1.f + e);
}
__device__ __forceinline__ float dsigf(float x) {
    float s = sigf(x);              // s in (0,1) -> non-negative branch
    return 1.f / (1.f + expf(-s));
}
__device__ __forceinline__ float clampf(float v, float lo, float hi) {
    return fminf(fmaxf(v, lo), hi);
}

// ---------------------------------------------------------------------------
// Kernel 1: per-anchor masked max-class score (key for top-k)
// ---------------------------------------------------------------------------
__global__ __launch_bounds__(256) void k_maxscore(Ptrs P) {
    if (blockIdx.x == 0 && blockIdx.y == 0 && threadIdx.x == 0) g_redo = 0;
    int b = blockIdx.y;
    int a = blockIdx.x * 256 + threadIdx.x;
    if (a >= NTOT) return;

    int l;
    if      (a < 15360) l = 0;
    else if (a < 19200) l = 1;
    else if (a < 20160) l = 2;
    else if (a < 20400) l = 3;
    else                l = 4;
    int r  = a - c_off[l];
    int HW = c_HW[l];

    const float* loc = P.p[4 * l + 3];
    float key = 0.f;
    float ls = sigf(loc[(size_t)b * HW + r]);
    if (ls >= 0.01f) {
        const float* cp = P.p[4 * l] + ((size_t)b * NUM_CLASSES) * HW + r;
        float m = -3.402823466e38f;
        #pragma unroll 8
        for (int c = 0; c < NUM_CLASSES; c++)
            m = fmaxf(m, cp[(size_t)c * HW]);
        key = dsigf(m);
    }
    g_key[(size_t)b * NTOT + a] = key;
}

// ---------------------------------------------------------------------------
// Kernel 2: per-image top-1000 by (key desc, idx asc). Radix-select threshold
// (warp-aggregated histogram atomics, parallel suffix-sum bin pick) then
// stable compaction + bitonic sort.
// ---------------------------------------------------------------------------
__global__ __launch_bounds__(1024) void k_select() {
    int b   = blockIdx.x;
    int tid = threadIdx.x;
    int lane = tid & 31, wid = tid >> 5;
    const unsigned* keys = reinterpret_cast<const unsigned*>(g_key) + (size_t)b * NTOT;

    __shared__ unsigned hist[256];
    __shared__ unsigned sfx[256];
    __shared__ unsigned s_prefix;
    __shared__ int s_m;
    __shared__ unsigned long long sel[1024];
    __shared__ int warp_tot[32];
    __shared__ int warp_scan[32];
    __shared__ int s_fill;
    __shared__ int s_runeq;

    if (tid == 0) { s_prefix = 0u; s_m = TOPK; }
    __syncthreads();

    // --- 4-round radix select (8 bits per round) to find threshold T ---
    for (int round = 0; round < 4; round++) {
        int shift = 24 - 8 * round;
        unsigned kmask = (round == 0) ? 0u : (0xFFFFFFFFu << (32 - 8 * round));
        if (tid < 256) hist[tid] = 0u;
        __syncthreads();
        unsigned pfx = s_prefix;
        int mcur = s_m;
        for (int i = tid; i < 20480; i += 1024) {   // padded uniform trip count
            bool v = i < NTOT;
            unsigned k = v ? keys[i] : 0u;
            bool act = v && ((k & kmask) == pfx);
            unsigned bin = (k >> shift) & 0xFFu;
            unsigned am = __ballot_sync(0xFFFFFFFFu, act);
            if (act) {
                unsigned peers = __match_any_sync(am, bin);
                if (lane == __ffs(peers) - 1)
                    atomicAdd(&hist[bin], (unsigned)__popc(peers));
            }
        }
        __syncthreads();
        // parallel inclusive suffix-sum of hist (warp 0, 8 chunks of 32)
        if (wid == 0) {
            unsigned carry = 0;
            #pragma unroll
            for (int ch = 7; ch >= 0; ch--) {
                unsigned v = hist[ch * 32 + lane];
                #pragma unroll
                for (int d = 1; d < 32; d <<= 1) {
                    unsigned o = __shfl_down_sync(0xFFFFFFFFu, v, d);
                    if (lane + d < 32) v += o;
                }
                sfx[ch * 32 + lane] = v + carry;
                carry += __shfl_sync(0xFFFFFFFFu, v, 0);   // chunk total
            }
        }
        __syncthreads();
        if (tid < 256) {
            unsigned S = sfx[tid];
            unsigned above = S - hist[tid];     // count strictly above this bin
            if (S >= (unsigned)mcur && above < (unsigned)mcur) {
                s_prefix = pfx | ((unsigned)tid << shift);
                s_m = mcur - (int)above;
            }
        }
        __syncthreads();
    }
    unsigned T = s_prefix;
    int meq = s_m;                          // how many ==T to take (by index order)

    sel[tid] = 0ull;
    if (tid == 0) { s_fill = 0; s_runeq = 0; }
    __syncthreads();

    // --- compaction: all >T (order irrelevant, sorted later); first meq ==T ---
    for (int base = 0; base < NTOT; base += 1024) {
        int i = base + tid;
        bool valid = i < NTOT;
        unsigned k = valid ? keys[i] : 0u;
        bool gt = valid && (k > T);
        bool eq = valid && (k == T);
        if (gt) {
            int p = atomicAdd(&s_fill, 1);
            sel[p] = (((unsigned long long)k) << 32) |
                     (unsigned long long)(0xFFFFFFFFu - (unsigned)i);
        }
        unsigned bal = __ballot_sync(0xFFFFFFFFu, eq);
        if (lane == 0) warp_tot[wid] = __popc(bal);
        __syncthreads();
        if (wid == 0) {
            int v = warp_tot[lane];
            #pragma unroll
            for (int d = 1; d < 32; d <<= 1) {
                int n = __shfl_up_sync(0xFFFFFFFFu, v, d);
                if (lane >= d) v += n;
            }
            warp_scan[lane] = v;            // inclusive scan
        }
        __syncthreads();
        int wbase = (wid == 0) ? 0 : warp_scan[wid - 1];
        int rank = s_runeq + wbase + __popc(bal & ((1u << lane) - 1u));
        if (eq && rank < meq) {
            int p = atomicAdd(&s_fill, 1);
            sel[p] = (((unsigned long long)k) << 32) |
                     (unsigned long long)(0xFFFFFFFFu - (unsigned)i);
        }
        __syncthreads();
        if (tid == 0) s_runeq += warp_scan[31];
        __syncthreads();
    }

    // --- bitonic sort descending on composite (key desc, idx asc) ---
    for (int k2 = 2; k2 <= 1024; k2 <<= 1) {
        for (int j = k2 >> 1; j > 0; j >>= 1) {
            __syncthreads();
            int ixj = tid ^ j;
            if (ixj > tid) {
                unsigned long long va = sel[tid], vb = sel[ixj];
                bool up = ((tid & k2) == 0);
                if (up ? (va < vb) : (va > vb)) { sel[tid] = vb; sel[ixj] = va; }
            }
        }
    }
    __syncthreads();
    g_sel[b * 1024 + tid] = (int)(0xFFFFFFFFu - (unsigned)(sel[tid] & 0xFFFFFFFFull));
}

// ---------------------------------------------------------------------------
// Kernel 3: gather per-class scores (thresholded) + decode proposal box
// one warp per selected row
// ---------------------------------------------------------------------------
__global__ __launch_bounds__(256) void k_gather(Ptrs P) {
    int w = (blockIdx.x * 256 + threadIdx.x) >> 5;
    int lane = threadIdx.x & 31;
    if (w >= B_IMG * TOPK) return;
    int b = w / TOPK;
    int j = w - b * TOPK;
    int a = g_sel[b * 1024 + j];

    int l;
    if      (a < 15360) l = 0;
    else if (a < 19200) l = 1;
    else if (a < 20160) l = 2;
    else if (a < 20400) l = 3;
    else                l = 4;
    int r  = a - c_off[l];
    int HW = c_HW[l];
    int W  = c_W[l];
    int yi = r / W;
    int xi = r - yi * W;

    const float* cls = P.p[4 * l + 0];
    const float* bb  = P.p[4 * l + 1];
    const float* shp = P.p[4 * l + 2];
    const float* loc = P.p[4 * l + 3];

    float maskf = (sigf(loc[(size_t)b * HW + r]) >= 0.01f) ? 1.f : 0.f;

    for (int c = lane; c < NUM_CLASSES; c += 32) {
        float v = cls[((size_t)b * NUM_CLASSES + c) * HW + r];
        float s = maskf * dsigf(v);
        g_sc[((size_t)b * NUM_CLASSES + c) * 1024 + j] = (s > 0.05f) ? s : 0.f;
    }

    if (lane == 0) {
        float st = c_stride[l];
        float xx = (float)xi * st, yy = (float)yi * st;
        float pw = 4.f * st;
        // guided anchor (delta2bbox with [0,0,dw,dh])
        float dw = clampf(shp[((size_t)b * 2 + 0) * HW + r], -MAX_RATIO_ANCHOR, MAX_RATIO_ANCHOR);
        float dh = clampf(shp[((size_t)b * 2 + 1) * HW + r], -MAX_RATIO_ANCHOR, MAX_RATIO_ANCHOR);
        float aw = pw * expf(dw);
        float ah = pw * expf(dh);
        float ax1 = xx - 0.5f * aw, ay1 = yy - 0.5f * ah;
        float ax2 = xx + 0.5f * aw, ay2 = yy + 0.5f * ah;
        // bbox decode (delta2bbox, clipped to image)
        float px = (ax1 + ax2) * 0.5f, py = (ay1 + ay2) * 0.5f;
        float w2 = ax2 - ax1,          h2 = ay2 - ay1;
        float dx  = bb[((size_t)b * 4 + 0) * HW + r];
        float dy  = bb[((size_t)b * 4 + 1) * HW + r];
        float dw2 = clampf(bb[((size_t)b * 4 + 2) * HW + r], -MAX_RATIO_BBOX, MAX_RATIO_BBOX);
        float dh2 = clampf(bb[((size_t)b * 4 + 3) * HW + r], -MAX_RATIO_BBOX, MAX_RATIO_BBOX);
        float gx = px + w2 * dx;
        float gy = py + h2 * dy;
        float gw = w2 * expf(dw2);
        float gh = h2 * expf(dh2);
        float x1 = clampf(gx - 0.5f * gw, 0.f, IMG_W);
        float y1 = clampf(gy - 0.5f * gh, 0.f, IMG_H);
        float x2 = clampf(gx + 0.5f * gw, 0.f, IMG_W);
        float y2 = clampf(gy + 0.5f * gh, 0.f, IMG_H);
        g_boxes[b * 1024 + j] = make_float4(x1, y1, x2, y2);
    }
}

// ---------------------------------------------------------------------------
// Kernel 4: per-class greedy NMS, capped pick list. One 128-thread block per
// (image, class). Classes are independent (class offsets 4096 > image extent
// make cross-class IoU exactly 0).
// Argmax = two REDUX ops (max score bits, min index among ties) per warp,
// double-buffered per-warp results -> ONE barrier per iteration.
// Sticky (degenerate zero-area pick that survives its own suppression) is
// detected as a re-pick of the same j on the next iteration: provably
// equivalent (it stays the class max forever). The reference then re-picks it
// for all remaining steps -> flag & stop; merge never advances past it.
// redo_pass: only recompute (cap=100) classes left "open" by phase A, and
// only when phase-B merge flagged g_redo.
// ---------------------------------------------------------------------------
__global__ __launch_bounds__(128) void k_classnms(int cap, int redo_pass) {
    int c = blockIdx.x;
    int b = blockIdx.y;
    int idx = b * NUM_CLASSES + c;
    if (redo_pass) {
        if (g_redo == 0) return;
        if (!(g_pick_cnt[idx] == K_CAP && g_pick_stk[idx] == 0)) return; // closed
    }
    int tid = threadIdx.x;
    int lane = tid & 31, wid = tid >> 5;

    __shared__ float4 sbox[TOPK];
    __shared__ unsigned long long wb[2][4];

    for (int i = tid; i < TOPK; i += 128)
        sbox[i] = g_boxes[b * 1024 + i];

    // register-resident scores: thread owns j = tid + 128*k (all >= 0)
    float s[8];
    const float* sp = g_sc + ((size_t)idx) * 1024;
    #pragma unroll
    for (int k = 0; k < 8; k++) {
        int j = tid + 128 * k;
        s[k] = (j < TOPK) ? sp[j] : 0.f;
    }
    __syncthreads();

    float offc = CLS_OFFSET * (float)c;
    int cnt = 0, sticky = 0, prevj = -1;
    float*          ps = g_pick_s + (size_t)idx * MAX_PER_IMG;
    unsigned short* pr = g_pick_r + (size_t)idx * MAX_PER_IMG;

    for (int t = 0; t <= cap; t++) {
        // per-thread best: max score bits, earliest j on ties (k ascending)
        unsigned bb = 0u, bj = 0u;
        #pragma unroll
        for (int k = 0; k < 8; k++) {
            unsigned bits = __float_as_uint(s[k]);   // s[k] >= 0
            if (bits > bb) { bb = bits; bj = (unsigned)(tid + 128 * k); }
        }
        // warp: max bits, then min j among ties
        unsigned M = __reduce_max_sync(0xFFFFFFFFu, bb);
        unsigned cand = (bb == M) ? bj : 0xFFFFFFFFu;
        unsigned J = __reduce_min_sync(0xFFFFFFFFu, cand);
        if (lane == 0)
            wb[t & 1][wid] = ((unsigned long long)M << 32)
                           | (unsigned long long)(0xFFFFFFFFu - J);
        __syncthreads();
        unsigned long long b0 = wb[t & 1][0];
        if (wb[t & 1][1] > b0) b0 = wb[t & 1][1];
        if (wb[t & 1][2] > b0) b0 = wb[t & 1][2];
        if (wb[t & 1][3] > b0) b0 = wb[t & 1][3];
        unsigned Mb = (unsigned)(b0 >> 32);
        if (Mb == 0u) break;                         // class exhausted
        int j = (int)(0xFFFFFFFFu - (unsigned)(b0 & 0xFFFFFFFFull));
        if (j == prevj) { sticky = 1; break; }       // pick survived itself
        if (t == cap) break;                          // cap reached (don't record)

        if (tid == 0) { ps[cnt] = __uint_as_float(Mb); pr[cnt] = (unsigned short)j; }
        cnt++;
        prevj = j;

        // suppression (offset boxes — matches reference rounding exactly)
        float4 pb = sbox[j];
        float px1 = pb.x + offc, py1 = pb.y + offc;
        float px2 = pb.z + offc, py2 = pb.w + offc;
        float a1 = (px2 - px1) * (py2 - py1);

        #pragma unroll
        for (int k = 0; k < 8; k++) {
            if (s[k] > 0.f) {
                int jj = tid + 128 * k;
                float4 q = sbox[jj];
                float qx1 = q.x + offc, qy1 = q.y + offc;
                float qx2 = q.z + offc, qy2 = q.w + offc;
                float ltx = fmaxf(px1, qx1), lty = fmaxf(py1, qy1);
                float rbx = fminf(px2, qx2), rby = fminf(py2, qy2);
                float ww = fmaxf(rbx - ltx, 0.f);
                float hh = fmaxf(rby - lty, 0.f);
                float inter = ww * hh;
                float a2 = (qx2 - qx1) * (qy2 - qy1);
                float iou = inter / (a1 + a2 - inter + 1e-6f);
                if (iou > 0.5f) s[k] = 0.f;
            }
        }
    }

    if (tid == 0) {
        g_pick_cnt[idx] = cnt;
        g_pick_stk[idx] = sticky;
    }
}

// ---------------------------------------------------------------------------
// Kernel 5: per-image merge of 80 sorted pick lists (100 steps).
// Tie-break = flattened key r*80+c asc (jax argmax over [N*C]).
// Sticky head never advances. In the validation pass (final=0), a class that
// hit cap K_CAP un-exhausted is "open": if its last-known score could beat or
// tie the winner, flag g_redo and abort (phases C/D fix it up).
// ---------------------------------------------------------------------------
__global__ __launch_bounds__(128) void k_merge(float* __restrict__ out, int final_pass) {
    if (final_pass && g_redo == 0) return;   // phase-B output already valid
    int b = blockIdx.x;
    int tid = threadIdx.x;
    int lane = tid & 31;

    __shared__ float          s_ps[NUM_CLASSES * MAX_PER_IMG];
    __shared__ unsigned short s_pr[NUM_CLASSES * MAX_PER_IMG];
    __shared__ int            s_cnt[NUM_CLASSES];
    __shared__ int            s_stk[NUM_CLASSES];
    __shared__ int            s_open[NUM_CLASSES];

    if (tid < NUM_CLASSES) {
        int cnt = g_pick_cnt[b * NUM_CLASSES + tid];
        int stk = g_pick_stk[b * NUM_CLASSES + tid];
        s_cnt[tid] = cnt;
        s_stk[tid] = stk;
        s_open[tid] = (!final_pass && cnt == K_CAP && stk == 0) ? 1 : 0;
    }
    __syncthreads();
    for (int c = tid >> 2; c < NUM_CLASSES; c += 32) {
        int cnt = s_cnt[c];
        for (int p = tid & 3; p < cnt; p += 4) {
            s_ps[c * MAX_PER_IMG + p] = g_pick_s[((size_t)(b * NUM_CLASSES + c)) * MAX_PER_IMG + p];
            s_pr[c * MAX_PER_IMG + p] = g_pick_r[((size_t)(b * NUM_CLASSES + c)) * MAX_PER_IMG + p];
        }
    }
    __syncthreads();
    if (tid >= 32) return;

    float* outB = out + 8;
    float* outS = outB + B_IMG * MAX_PER_IMG * 4;
    float* outC = outS + B_IMG * MAX_PER_IMG;

    // lane owns classes lane, lane+32, lane+64(<80)
    int p[3] = {0, 0, 0};
    int ndet = 0;
    bool valid = true;

    for (int t = 0; t < MAX_PER_IMG; t++) {
        unsigned sb = 0u, ky = 0xFFFFFFFFu, boundbits = 0u;
        #pragma unroll
        for (int q = 0; q < 3; q++) {
            int c = lane + 32 * q;
            if (c < NUM_CLASSES) {
                int pp = p[q], cnt = s_cnt[c];
                if (pp < cnt) {
                    unsigned key = (unsigned)s_pr[c * MAX_PER_IMG + pp] * 80u + (unsigned)c;
                    unsigned bits = __float_as_uint(s_ps[c * MAX_PER_IMG + pp]);
                    if (bits > sb || (bits == sb && key < ky)) { sb = bits; ky = key; }
                } else if (s_open[c]) {
                    unsigned bb2 = __float_as_uint(s_ps[c * MAX_PER_IMG + cnt - 1]);
                    if (bb2 > boundbits) boundbits = bb2;
                }
            }
        }
        unsigned M = __reduce_max_sync(0xFFFFFFFFu, sb);
        unsigned cand = (sb == M) ? ky : 0xFFFFFFFFu;
        unsigned K = __reduce_min_sync(0xFFFFFFFFu, cand);
        unsigned Bd = __reduce_max_sync(0xFFFFFFFFu, boundbits);

        // validation: an open class might hold a better (or tied) future pick
        if (Bd != 0u && (M == 0u || Bd >= M)) {
            if (lane == 0) g_redo = 1;
            valid = false;
            break;
        }

        if (M == 0u) {
            for (int tt = t + lane; tt < MAX_PER_IMG; tt += 32) {
                int o = b * MAX_PER_IMG + tt;
                outB[o * 4 + 0] = 0.f; outB[o * 4 + 1] = 0.f;
                outB[o * 4 + 2] = 0.f; outB[o * 4 + 3] = 0.f;
                outS[o] = 0.f;
                outC[o] = -1.f;
            }
            break;
        }

        int c = (int)(K % 80u);
        int r = (int)(K / 80u);

        if (lane == 0) {
            float4 bx = g_boxes[b * 1024 + r];
            int o = b * MAX_PER_IMG + t;
            outB[o * 4 + 0] = bx.x;
            outB[o * 4 + 1] = bx.y;
            outB[o * 4 + 2] = bx.z;
            outB[o * 4 + 3] = bx.w;
            outS[o] = __uint_as_float(M);
            outC[o] = (float)c;
        }
        ndet++;

        // advance owner (unless sticky at tail: reference re-picks forever)
        int q = -1;
        if (c == lane) q = 0;
        else if (c == lane + 32) q = 1;
        else if (c == lane + 64) q = 2;
        if (q >= 0) {
            if (!(s_stk[c] && p[q] == s_cnt[c] - 1)) p[q]++;
        }
    }

    if (valid && lane == 0) out[b] = (float)ndet;
}

// ---------------------------------------------------------------------------
// Launch
// ---------------------------------------------------------------------------
extern "C" void kernel_launch(void* const* d_in, const int* in_sizes, int n_in,
                              void* d_out, int out_size) {
    (void)in_sizes; (void)n_in; (void)out_size;
    Ptrs P;
    for (int i = 0; i < 20; i++) P.p[i] = (const float*)d_in[i];
    float* out = (float*)d_out;

    dim3 g1((NTOT + 255) / 256, B_IMG);
    k_maxscore<<<g1, 256>>>(P);
    k_select<<<B_IMG, 1024>>>();
    k_gather<<<(B_IMG * TOPK * 32 + 255) / 256, 256>>>(P);
    k_classnms<<<dim3(NUM_CLASSES, B_IMG), 128>>>(K_CAP, 0);       // phase A
    k_merge<<<B_IMG, 128>>>(out, 0);                               // phase B
    k_classnms<<<dim3(NUM_CLASSES, B_IMG), 128>>>(MAX_PER_IMG, 1); // phase C
    k_merge<<<B_IMG, 128>>>(out, 1);                               // phase D
}

// round 5
// speedup vs baseline: 6.8190x; 1.2514x over previous
#include <cuda_runtime.h>
#include <cstdint>

// ---------------------------------------------------------------------------
// Problem constants
// ---------------------------------------------------------------------------
#define NUM_CLASSES 80
#define B_IMG 8
#define NTOT 20460            // total anchors per image across 5 levels
#define TOPK 1000
#define MAX_PER_IMG 100
#define K_CAP 16              // phase-A per-class pick cap
#define IMG_H 768.0f
#define IMG_W 1280.0f
#define CLS_OFFSET 4096.0f
#define MAX_RATIO_ANCHOR 13.815510557964274f   // |log(1e-6)|
#define MAX_RATIO_BBOX   4.135166556742356f    // |log(16/1000)|

__device__ __constant__ int   c_HW[5]     = {15360, 3840, 960, 240, 60};
__device__ __constant__ int   c_W[5]      = {160, 80, 40, 20, 10};
__device__ __constant__ int   c_off[5]    = {0, 15360, 19200, 20160, 20400};
__device__ __constant__ float c_stride[5] = {8.f, 16.f, 32.f, 64.f, 128.f};

// ---------------------------------------------------------------------------
// Scratch (device globals; no runtime allocation allowed)
// ---------------------------------------------------------------------------
__device__ float  g_key[B_IMG * NTOT];          // per-anchor masked max score
__device__ int    g_sel[B_IMG * 1024];          // selected anchor ids (sorted)
__device__ float  g_sc[B_IMG * NUM_CLASSES * 1024]; // class-major scores (phase A may write back suppressed state)
__device__ float4 g_boxes[B_IMG * 1024];        // decoded proposals

// per-class NMS pick lists
__device__ float          g_pick_s[B_IMG * NUM_CLASSES * MAX_PER_IMG];
__device__ unsigned short g_pick_r[B_IMG * NUM_CLASSES * MAX_PER_IMG];
__device__ int            g_pick_cnt[B_IMG * NUM_CLASSES];
__device__ int            g_pick_stk[B_IMG * NUM_CLASSES];
__device__ int            g_open[B_IMG * NUM_CLASSES];   // open = capped w/ state written back
__device__ int            g_need[B_IMG * NUM_CLASSES];   // merge-B: class must be deepened
__device__ int            g_redo;

struct Ptrs { const float* p[20]; };

// ---------------------------------------------------------------------------
// Numerics matching jax
// ---------------------------------------------------------------------------
__device__ __forceinline__ float sigf(float x) {
    if (x >= 0.f) return 1.f / (1.f + expf(-x));
    float e = expf(x);
    return e / (1.f + e);
}
__device__ __forceinline__ float dsigf(float x) {
    float s = sigf(x);              // s in (0,1) -> non-negative branch
    return 1.f / (1.f + expf(-s));
}
__device__ __forceinline__ float clampf(float v, float lo, float hi) {
    return fminf(fmaxf(v, lo), hi);
}

// ---------------------------------------------------------------------------
// Kernel 1: per-anchor masked max-class score (key for top-k)
// ---------------------------------------------------------------------------
__global__ __launch_bounds__(256) void k_maxscore(Ptrs P) {
    if (blockIdx.x == 0 && blockIdx.y == 0 && threadIdx.x == 0) g_redo = 0;
    int b = blockIdx.y;
    int a = blockIdx.x * 256 + threadIdx.x;
    if (a >= NTOT) return;

    int l;
    if      (a < 15360) l = 0;
    else if (a < 19200) l = 1;
    else if (a < 20160) l = 2;
    else if (a < 20400) l = 3;
    else                l = 4;
    int r  = a - c_off[l];
    int HW = c_HW[l];

    const float* loc = P.p[4 * l + 3];
    float key = 0.f;
    float ls = sigf(loc[(size_t)b * HW + r]);
    if (ls >= 0.01f) {
        const float* cp = P.p[4 * l] + ((size_t)b * NUM_CLASSES) * HW + r;
        float m = -3.402823466e38f;
        #pragma unroll 8
        for (int c = 0; c < NUM_CLASSES; c++)
            m = fmaxf(m, cp[(size_t)c * HW]);
        key = dsigf(m);
    }
    g_key[(size_t)b * NTOT + a] = key;
}

// ---------------------------------------------------------------------------
// Kernel 2: per-image top-1000 by (key desc, idx asc). Radix-select threshold
// (warp-aggregated histogram atomics, parallel suffix-sum bin pick) then
// stable compaction + bitonic sort.
// ---------------------------------------------------------------------------
__global__ __launch_bounds__(1024) void k_select() {
    int b   = blockIdx.x;
    int tid = threadIdx.x;
    int lane = tid & 31, wid = tid >> 5;
    const unsigned* keys = reinterpret_cast<const unsigned*>(g_key) + (size_t)b * NTOT;

    __shared__ unsigned hist[256];
    __shared__ unsigned sfx[256];
    __shared__ unsigned s_prefix;
    __shared__ int s_m;
    __shared__ unsigned long long sel[1024];
    __shared__ int warp_tot[32];
    __shared__ int warp_scan[32];
    __shared__ int s_fill;
    __shared__ int s_runeq;

    if (tid == 0) { s_prefix = 0u; s_m = TOPK; }
    __syncthreads();

    // --- 4-round radix select (8 bits per round) to find threshold T ---
    for (int round = 0; round < 4; round++) {
        int shift = 24 - 8 * round;
        unsigned kmask = (round == 0) ? 0u : (0xFFFFFFFFu << (32 - 8 * round));
        if (tid < 256) hist[tid] = 0u;
        __syncthreads();
        unsigned pfx = s_prefix;
        int mcur = s_m;
        for (int i = tid; i < 20480; i += 1024) {   // padded uniform trip count
            bool v = i < NTOT;
            unsigned k = v ? keys[i] : 0u;
            bool act = v && ((k & kmask) == pfx);
            unsigned bin = (k >> shift) & 0xFFu;
            unsigned am = __ballot_sync(0xFFFFFFFFu, act);
            if (act) {
                unsigned peers = __match_any_sync(am, bin);
                if (lane == __ffs(peers) - 1)
                    atomicAdd(&hist[bin], (unsigned)__popc(peers));
            }
        }
        __syncthreads();
        // parallel inclusive suffix-sum of hist (warp 0, 8 chunks of 32)
        if (wid == 0) {
            unsigned carry = 0;
            #pragma unroll
            for (int ch = 7; ch >= 0; ch--) {
                unsigned v = hist[ch * 32 + lane];
                #pragma unroll
                for (int d = 1; d < 32; d <<= 1) {
                    unsigned o = __shfl_down_sync(0xFFFFFFFFu, v, d);
                    if (lane + d < 32) v += o;
                }
                sfx[ch * 32 + lane] = v + carry;
                carry += __shfl_sync(0xFFFFFFFFu, v, 0);   // chunk total
            }
        }
        __syncthreads();
        if (tid < 256) {
            unsigned S = sfx[tid];
            unsigned above = S - hist[tid];     // count strictly above this bin
            if (S >= (unsigned)mcur && above < (unsigned)mcur) {
                s_prefix = pfx | ((unsigned)tid << shift);
                s_m = mcur - (int)above;
            }
        }
        __syncthreads();
    }
    unsigned T = s_prefix;
    int meq = s_m;                          // how many ==T to take (by index order)

    sel[tid] = 0ull;
    if (tid == 0) { s_fill = 0; s_runeq = 0; }
    __syncthreads();

    // --- compaction: all >T (order irrelevant, sorted later); first meq ==T ---
    for (int base = 0; base < NTOT; base += 1024) {
        int i = base + tid;
        bool valid = i < NTOT;
        unsigned k = valid ? keys[i] : 0u;
        bool gt = valid && (k > T);
        bool eq = valid && (k == T);
        if (gt) {
            int p = atomicAdd(&s_fill, 1);
            sel[p] = (((unsigned long long)k) << 32) |
                     (unsigned long long)(0xFFFFFFFFu - (unsigned)i);
        }
        unsigned bal = __ballot_sync(0xFFFFFFFFu, eq);
        if (lane == 0) warp_tot[wid] = __popc(bal);
        __syncthreads();
        if (wid == 0) {
            int v = warp_tot[lane];
            #pragma unroll
            for (int d = 1; d < 32; d <<= 1) {
                int n = __shfl_up_sync(0xFFFFFFFFu, v, d);
                if (lane >= d) v += n;
            }
            warp_scan[lane] = v;            // inclusive scan
        }
        __syncthreads();
        int wbase = (wid == 0) ? 0 : warp_scan[wid - 1];
        int rank = s_runeq + wbase + __popc(bal & ((1u << lane) - 1u));
        if (eq && rank < meq) {
            int p = atomicAdd(&s_fill, 1);
            sel[p] = (((unsigned long long)k) << 32) |
                     (unsigned long long)(0xFFFFFFFFu - (unsigned)i);
        }
        __syncthreads();
        if (tid == 0) s_runeq += warp_scan[31];
        __syncthreads();
    }

    // --- bitonic sort descending on composite (key desc, idx asc) ---
    for (int k2 = 2; k2 <= 1024; k2 <<= 1) {
        for (int j = k2 >> 1; j > 0; j >>= 1) {
            __syncthreads();
            int ixj = tid ^ j;
            if (ixj > tid) {
                unsigned long long va = sel[tid], vb = sel[ixj];
                bool up = ((tid & k2) == 0);
                if (up ? (va < vb) : (va > vb)) { sel[tid] = vb; sel[ixj] = va; }
            }
        }
    }
    __syncthreads();
    g_sel[b * 1024 + tid] = (int)(0xFFFFFFFFu - (unsigned)(sel[tid] & 0xFFFFFFFFull));
}

// ---------------------------------------------------------------------------
// Kernel 3: gather per-class scores (thresholded) + decode proposal box
// one warp per selected row
// ---------------------------------------------------------------------------
__global__ __launch_bounds__(256) void k_gather(Ptrs P) {
    int w = (blockIdx.x * 256 + threadIdx.x) >> 5;
    int lane = threadIdx.x & 31;
    if (w >= B_IMG * TOPK) return;
    int b = w / TOPK;
    int j = w - b * TOPK;
    int a = g_sel[b * 1024 + j];

    int l;
    if      (a < 15360) l = 0;
    else if (a < 19200) l = 1;
    else if (a < 20160) l = 2;
    else if (a < 20400) l = 3;
    else                l = 4;
    int r  = a - c_off[l];
    int HW = c_HW[l];
    int W  = c_W[l];
    int yi = r / W;
    int xi = r - yi * W;

    const float* cls = P.p[4 * l + 0];
    const float* bb  = P.p[4 * l + 1];
    const float* shp = P.p[4 * l + 2];
    const float* loc = P.p[4 * l + 3];

    float maskf = (sigf(loc[(size_t)b * HW + r]) >= 0.01f) ? 1.f : 0.f;

    for (int c = lane; c < NUM_CLASSES; c += 32) {
        float v = cls[((size_t)b * NUM_CLASSES + c) * HW + r];
        float s = maskf * dsigf(v);
        g_sc[((size_t)b * NUM_CLASSES + c) * 1024 + j] = (s > 0.05f) ? s : 0.f;
    }

    if (lane == 0) {
        float st = c_stride[l];
        float xx = (float)xi * st, yy = (float)yi * st;
        float pw = 4.f * st;
        // guided anchor (delta2bbox with [0,0,dw,dh])
        float dw = clampf(shp[((size_t)b * 2 + 0) * HW + r], -MAX_RATIO_ANCHOR, MAX_RATIO_ANCHOR);
        float dh = clampf(shp[((size_t)b * 2 + 1) * HW + r], -MAX_RATIO_ANCHOR, MAX_RATIO_ANCHOR);
        float aw = pw * expf(dw);
        float ah = pw * expf(dh);
        float ax1 = xx - 0.5f * aw, ay1 = yy - 0.5f * ah;
        float ax2 = xx + 0.5f * aw, ay2 = yy + 0.5f * ah;
        // bbox decode (delta2bbox, clipped to image)
        float px = (ax1 + ax2) * 0.5f, py = (ay1 + ay2) * 0.5f;
        float w2 = ax2 - ax1,          h2 = ay2 - ay1;
        float dx  = bb[((size_t)b * 4 + 0) * HW + r];
        float dy  = bb[((size_t)b * 4 + 1) * HW + r];
        float dw2 = clampf(bb[((size_t)b * 4 + 2) * HW + r], -MAX_RATIO_BBOX, MAX_RATIO_BBOX);
        float dh2 = clampf(bb[((size_t)b * 4 + 3) * HW + r], -MAX_RATIO_BBOX, MAX_RATIO_BBOX);
        float gx = px + w2 * dx;
        float gy = py + h2 * dy;
        float gw = w2 * expf(dw2);
        float gh = h2 * expf(dh2);
        float x1 = clampf(gx - 0.5f * gw, 0.f, IMG_W);
        float y1 = clampf(gy - 0.5f * gh, 0.f, IMG_H);
        float x2 = clampf(gx + 0.5f * gw, 0.f, IMG_W);
        float y2 = clampf(gy + 0.5f * gh, 0.f, IMG_H);
        g_boxes[b * 1024 + j] = make_float4(x1, y1, x2, y2);
    }
}

// ---------------------------------------------------------------------------
// Kernel 4: per-class greedy NMS. One 128-thread block per (image, class).
// Classes independent (class offsets 4096 > image extent -> cross-class IoU 0).
// mode 0 (phase A): fresh run capped at K_CAP picks. If capped ("open"),
//   write the post-suppression score state back to g_sc so phase C can RESUME.
// mode 1 (phase C): only if merge-B flagged this class as needed; resume from
//   pick cnt+1 using the written-back state, up to MAX_PER_IMG picks.
// Sticky detection: a pick re-picked on the next iteration (degenerate
// zero-area box that survives its own suppression) stays max forever ->
// flag & stop; the merge repeats it for all remaining steps (= reference).
// ---------------------------------------------------------------------------
__global__ __launch_bounds__(128) void k_classnms(int mode) {
    int c = blockIdx.x;
    int b = blockIdx.y;
    int idx = b * NUM_CLASSES + c;
    if (mode == 1 && (g_redo == 0 || g_need[idx] == 0)) return;
    int tid = threadIdx.x;
    int lane = tid & 31, wid = tid >> 5;

    __shared__ float4 sbox[TOPK];
    __shared__ unsigned long long wb[2][4];

    for (int i = tid; i < TOPK; i += 128)
        sbox[i] = g_boxes[b * 1024 + i];

    // register-resident scores: thread owns j = tid + 128*k (all >= 0)
    float s[8];
    float* sp = g_sc + ((size_t)idx) * 1024;
    #pragma unroll
    for (int k = 0; k < 8; k++) {
        int j = tid + 128 * k;
        s[k] = (j < TOPK) ? sp[j] : 0.f;
    }
    __syncthreads();

    int cap = (mode == 1) ? MAX_PER_IMG : K_CAP;
    int cnt = (mode == 1) ? g_pick_cnt[idx] : 0;
    float*          ps = g_pick_s + (size_t)idx * MAX_PER_IMG;
    unsigned short* pr = g_pick_r + (size_t)idx * MAX_PER_IMG;
    int prevj = (mode == 1) ? (int)pr[cnt - 1] : -1;

    float offc = CLS_OFFSET * (float)c;
    int sticky = 0, open = 0, it = 0;

    for (;;) {
        // per-thread best: max score bits, earliest j on ties (k ascending)
        unsigned bb = 0u, bj = 0u;
        #pragma unroll
        for (int k = 0; k < 8; k++) {
            unsigned bits = __float_as_uint(s[k]);   // s[k] >= 0
            if (bits > bb) { bb = bits; bj = (unsigned)(tid + 128 * k); }
        }
        unsigned M = __reduce_max_sync(0xFFFFFFFFu, bb);
        unsigned cand = (bb == M) ? bj : 0xFFFFFFFFu;
        unsigned J = __reduce_min_sync(0xFFFFFFFFu, cand);
        if (lane == 0)
            wb[it & 1][wid] = ((unsigned long long)M << 32)
                            | (unsigned long long)(0xFFFFFFFFu - J);
        __syncthreads();
        unsigned long long b0 = wb[it & 1][0];
        if (wb[it & 1][1] > b0) b0 = wb[it & 1][1];
        if (wb[it & 1][2] > b0) b0 = wb[it & 1][2];
        if (wb[it & 1][3] > b0) b0 = wb[it & 1][3];
        it++;
        unsigned Mb = (unsigned)(b0 >> 32);
        if (Mb == 0u) break;                         // class exhausted
        int j = (int)(0xFFFFFFFFu - (unsigned)(b0 & 0xFFFFFFFFull));
        if (j == prevj) { sticky = 1; break; }       // pick survived itself
        if (cnt == cap) { open = 1; break; }         // capped (candidate not recorded)

        if (tid == 0) { ps[cnt] = __uint_as_float(Mb); pr[cnt] = (unsigned short)j; }
        cnt++;
        prevj = j;

        // suppression (offset boxes — matches reference rounding exactly)
        float4 pb = sbox[j];
        float px1 = pb.x + offc, py1 = pb.y + offc;
        float px2 = pb.z + offc, py2 = pb.w + offc;
        float a1 = (px2 - px1) * (py2 - py1);

        #pragma unroll
        for (int k = 0; k < 8; k++) {
            if (s[k] > 0.f) {
                int jj = tid + 128 * k;
                float4 q = sbox[jj];
                float qx1 = q.x + offc, qy1 = q.y + offc;
                float qx2 = q.z + offc, qy2 = q.w + offc;
                float ltx = fmaxf(px1, qx1), lty = fmaxf(py1, qy1);
                float rbx = fminf(px2, qx2), rby = fminf(py2, qy2);
                float ww = fmaxf(rbx - ltx, 0.f);
                float hh = fmaxf(rby - lty, 0.f);
                float inter = ww * hh;
                float a2 = (qx2 - qx1) * (qy2 - qy1);
                float iou = inter / (a1 + a2 - inter + 1e-6f);
                if (iou > 0.5f) s[k] = 0.f;
            }
        }
    }

    // open classes persist suppressed state so phase C can resume exactly
    if (mode == 0 && open) {
        #pragma unroll
        for (int k = 0; k < 8; k++) {
            int j = tid + 128 * k;
            if (j < TOPK) sp[j] = s[k];
        }
    }

    if (tid == 0) {
        g_pick_cnt[idx] = cnt;
        g_pick_stk[idx] = sticky;
        g_open[idx] = (mode == 0) ? open : 0;
    }
}

// ---------------------------------------------------------------------------
// Kernel 5: per-image merge as a SORT. The 100-step greedy merge of sorted
// per-class lists equals: sort all picks by (score bits desc, key=r*80+c asc);
// emit the prefix; the FIRST sticky element in sorted order repeats forever
// (degenerate box is argmax from then on). Sticky bit is embedded in the low
// word (keys are globally unique so it never affects ordering).
// Phase B (final=0): also compute need[c] = open[c] && last_bits >= bits of
// the 100th output (conservative superset; bound 0 if fewer than 100 emitted).
// Phase D (final=1): only if g_redo; exact re-merge with deepened lists.
// ---------------------------------------------------------------------------
__global__ __launch_bounds__(1024) void k_merge(float* __restrict__ out, int final_pass) {
    if (final_pass && g_redo == 0) return;
    int b = blockIdx.x;
    int tid = threadIdx.x;
    int lane = tid & 31, wid = tid >> 5;

    __shared__ unsigned long long arr[2048];
    __shared__ int s_n;
    __shared__ int s_fs;
    __shared__ unsigned      s_last[NUM_CLASSES];
    __shared__ unsigned char s_opn[NUM_CLASSES];

    arr[tid] = 0ull;
    arr[tid + 1024] = 0ull;
    if (tid == 0) { s_n = 0; s_fs = 1 << 30; }
    __syncthreads();

    // load candidates (order within arr irrelevant; sorted below)
    for (int c = wid; c < NUM_CLASSES; c += 32) {
        int idx = b * NUM_CLASSES + c;
        int cnt = g_pick_cnt[idx];
        int stk = g_pick_stk[idx];
        int base = 0;
        if (lane == 0) {
            base = atomicAdd(&s_n, cnt);
            s_last[c] = cnt ? __float_as_uint(g_pick_s[(size_t)idx * MAX_PER_IMG + cnt - 1]) : 0u;
            s_opn[c] = (unsigned char)g_open[idx];
        }
        base = __shfl_sync(0xFFFFFFFFu, base, 0);
        for (int p = lane; p < cnt; p += 32) {
            unsigned bits = __float_as_uint(g_pick_s[(size_t)idx * MAX_PER_IMG + p]);
            unsigned key  = (unsigned)g_pick_r[(size_t)idx * MAX_PER_IMG + p] * 80u + (unsigned)c;
            unsigned st   = (stk && p == cnt - 1) ? 1u : 0u;
            int pos = base + p;
            if (pos < 2048)
                arr[pos] = ((unsigned long long)bits << 32)
                         | (unsigned long long)(0xFFFFFFFFu - ((key << 1) | st));
        }
    }
    __syncthreads();

    // bitonic sort descending over 2048 (zero padding sinks to the end)
    for (int k2 = 2; k2 <= 2048; k2 <<= 1) {
        for (int j = k2 >> 1; j > 0; j >>= 1) {
            int a = ((tid & ~(j - 1)) << 1) | (tid & (j - 1));
            int bx = a + j;
            unsigned long long va = arr[a], vb = arr[bx];
            bool desc = ((a & k2) == 0);
            if (desc ? (va < vb) : (va > vb)) { arr[a] = vb; arr[bx] = va; }
            __syncthreads();
        }
    }

    // locate first sticky in sorted order
    #pragma unroll
    for (int q = 0; q < 2; q++) {
        int i2 = tid + q * 1024;
        unsigned long long e = arr[i2];
        if (e != 0ull) {
            unsigned v = 0xFFFFFFFFu - (unsigned)(e & 0xFFFFFFFFull);
            if (v & 1u) atomicMin(&s_fs, i2);
        }
    }
    __syncthreads();

    int fs = s_fs;
    int ncand = s_n; if (ncand > 2048) ncand = 2048;

    float* outB = out + 8;
    float* outS = outB + B_IMG * MAX_PER_IMG * 4;
    float* outC = outS + B_IMG * MAX_PER_IMG;

    // bits of the 100th output (0 if fewer than 100 emitted)
    unsigned out100 = 0u;
    {
        int src99 = (99 <= fs) ? 99 : fs;
        bool has99 = (fs < 2048) ? true : (99 < ncand);
        if (has99) out100 = (unsigned)(arr[src99] >> 32);
    }

    if (tid < MAX_PER_IMG) {
        int t = tid;
        int src = (t <= fs) ? t : fs;
        bool has = (fs < 2048) ? true : (t < ncand);
        int o = b * MAX_PER_IMG + t;
        if (has) {
            unsigned long long e = arr[src];
            unsigned v = 0xFFFFFFFFu - (unsigned)(e & 0xFFFFFFFFull);
            unsigned key = v >> 1;
            int c = (int)(key % 80u);
            int r = (int)(key / 80u);
            float4 bx = g_boxes[b * 1024 + r];
            outB[o * 4 + 0] = bx.x;
            outB[o * 4 + 1] = bx.y;
            outB[o * 4 + 2] = bx.z;
            outB[o * 4 + 3] = bx.w;
            outS[o] = __uint_as_float((unsigned)(e >> 32));
            outC[o] = (float)c;
        } else {
            outB[o * 4 + 0] = 0.f; outB[o * 4 + 1] = 0.f;
            outB[o * 4 + 2] = 0.f; outB[o * 4 + 3] = 0.f;
            outS[o] = 0.f;
            outC[o] = -1.f;
        }
    }
    if (tid == 0) {
        int ndet = (fs < 2048) ? MAX_PER_IMG : (ncand < MAX_PER_IMG ? ncand : MAX_PER_IMG);
        out[b] = (float)ndet;
    }

    // phase B: mark classes whose unknown (deeper) picks could matter
    if (!final_pass && tid < NUM_CLASSES) {
        int need = (s_opn[tid] && s_last[tid] >= out100) ? 1 : 0;
        g_need[b * NUM_CLASSES + tid] = need;
        if (need) g_redo = 1;
    }
}

// ---------------------------------------------------------------------------
// Launch
// ---------------------------------------------------------------------------
extern "C" void kernel_launch(void* const* d_in, const int* in_sizes, int n_in,
                              void* d_out, int out_size) {
    (void)in_sizes; (void)n_in; (void)out_size;
    Ptrs P;
    for (int i = 0; i < 20; i++) P.p[i] = (const float*)d_in[i];
    float* out = (float*)d_out;

    dim3 g1((NTOT + 255) / 256, B_IMG);
    k_maxscore<<<g1, 256>>>(P);
    k_select<<<B_IMG, 1024>>>();
    k_gather<<<(B_IMG * TOPK * 32 + 255) / 256, 256>>>(P);
    k_classnms<<<dim3(NUM_CLASSES, B_IMG), 128>>>(0);   // phase A (cap 16)
    k_merge<<<B_IMG, 1024>>>(out, 0);                   // phase B (+ need marking)
    k_classnms<<<dim3(NUM_CLASSES, B_IMG), 128>>>(1);   // phase C (resume needed classes)
    k_merge<<<B_IMG, 1024>>>(out, 1);                   // phase D (only if redo)
}